// round 10
// baseline (speedup 1.0000x reference)
#include <cuda_runtime.h>
#include <cuda_fp16.h>
#include <math.h>

#define DIMK   1024
#define IMG_H  512
#define IMG_W  1408
#define CROPS  224
#define NCC    6
#define NBB    32
#define NBOX   64
#define NIMG   384
#define O1 56
#define O2 14
#define O3 7
#define N1 ((long long)NIMG*O1*O1)   // 1204224
#define N2 ((long long)NIMG*O2*O2)   // 75264
#define N3 ((long long)NIMG*O3*O3)   // 18816
#define K1 147
#define K2 576
#define K3 2304
// padded crops: [ch][img][227][228]
#define CP_PW 228
#define CP_IMG (227*228)
#define CP_CH  (NIMG*CP_IMG)
// padded h2: [ic][img][15][15]
#define H2P_IMG 225
#define H2P_IC  (NIMG*H2P_IMG)

// ---------------- scratch ----------------
__device__ float  g_theta[NIMG*6];
__device__ int    g_valid[NIMG];
__device__ __align__(16) __half g_cropsp[3LL*CP_CH];
__device__ __half g_h1h[64LL*N1];
__device__ __align__(16) __half g_h2p[256LL*H2P_IC];
__device__ float  g_h3T[(long long)N3*1024];     // transposed: [n][oc]
__device__ float  g_tok[(long long)NIMG*50*DIMK];
__device__ float  g_S[NIMG*DIMK];
__device__ float  g_EMB[NIMG*DIMK];
__device__ unsigned g_wqp[512*1024], g_wvp[512*1024];
__device__ unsigned g_wkTp[512*1024], g_wop[512*1024];
__device__ unsigned g_Mp[512*1024], g_Wvop[512*1024];
__device__ unsigned g_w1p[64*80];
__device__ unsigned g_w2p[256*288];
__device__ unsigned g_w3p[1024*1152];
__device__ unsigned g_tok0p[384*512];
__device__ unsigned g_CTXp[384*512];

// ---------------- halo zero kernels ----------------
__global__ void haloc_kernel()
{
    long long base = (long long)blockIdx.x*CP_IMG;   // blockIdx.x = ch*NIMG+img
    __half z = __ushort_as_half((unsigned short)0);
    for (int t = threadIdx.x; t < 3*CP_PW; t += 256) {
        int r = t/CP_PW, c = t - (t/CP_PW)*CP_PW;
        int row = (r == 0) ? 0 : (224 + r);          // rows 0,225,226
        g_cropsp[base + row*CP_PW + c] = z;
    }
    for (int t = threadIdx.x; t < 224*4; t += 256) {
        int row = 1 + (t >> 2); int c4 = t & 3;
        int col = (c4 == 0) ? 0 : (224 + c4);        // cols 0,225,226,227
        g_cropsp[base + row*CP_PW + col] = z;
    }
}
__global__ void haloh2_kernel()
{
    long long i = (long long)blockIdx.x*256 + threadIdx.x;
    if (i >= 256LL*NIMG*29) return;
    int e = (int)(i % 29); long long pair = i / 29;
    int off = (e < 15) ? (14*15 + e) : ((e - 15)*15 + 14);
    g_h2p[pair*225 + off] = __ushort_as_half((unsigned short)0);
}

// ---------------- pack kernels ----------------
__global__ void packA_kernel(const float* __restrict__ src, unsigned* __restrict__ dst,
                             int Ms, int Ks, int BMp, int Kpad, long long total)
{
    long long i = (long long)blockIdx.x*256 + threadIdx.x;
    if (i >= total) return;
    int NCH = Kpad/32;
    int mloc = (int)(i % BMp); long long r = i / BMp;
    int kp = (int)(r % 16); r /= 16;
    int chunk = (int)(r % NCH); int mblk = (int)(r / NCH);
    int m = mblk*BMp + mloc, k = chunk*32 + kp*2;
    float v0 = (m < Ms && k   < Ks) ? src[(long long)m*Ks + k]   : 0.f;
    float v1 = (m < Ms && k+1 < Ks) ? src[(long long)m*Ks + k+1] : 0.f;
    __half2 h = __floats2half2_rn(v0, v1);
    dst[i] = *reinterpret_cast<unsigned*>(&h);
}
__global__ void packBd_kernel(const float* __restrict__ src, unsigned* __restrict__ dst,
                              int Kd, int Nd, int transb)
{
    long long i = (long long)blockIdx.x*256 + threadIdx.x;
    if (i >= (long long)(Kd/2)*Nd) return;
    int n = (int)(i % Nd); long long r = i / Nd;
    int kp = (int)(r % 16); int chunk = (int)(r / 16);
    int k = chunk*32 + kp*2;
    float v0 = transb ? src[(long long)n*Kd + k]   : src[(long long)k*Nd + n];
    float v1 = transb ? src[(long long)n*Kd + k+1] : src[(long long)(k+1)*Nd + n];
    __half2 h = __floats2half2_rn(v0, v1);
    dst[i] = *reinterpret_cast<unsigned*>(&h);
}

// ---------------- theta ----------------
__global__ void theta_kernel(const float* __restrict__ boxes, const float* __restrict__ la,
                             const float* __restrict__ l2i, const float* __restrict__ aug,
                             const float* __restrict__ thw, const float* __restrict__ thb)
{
    int t = blockIdx.x*blockDim.x + threadIdx.x;
    if (t >= NIMG) return;
    int c = t % NCC; int n = t / NCC; int b = n / NBB; int nb = n % NBB;
    const float* bx = boxes + (b*NBB + nb)*9;
    float r[4];
    #pragma unroll
    for (int i = 0; i < 4; i++) {
        float s = thb[i];
        #pragma unroll
        for (int j = 0; j < 9; j++) s += bx[j]*thw[i*9+j];
        r[i] = tanhf(s);
    }
    const float* L = la + b*16;
    float cx = bx[0]-L[3], cy = bx[1]-L[7], cz = bx[2]-L[11];
    float a00=L[0],a01=L[1],a02=L[2],a10=L[4],a11=L[5],a12=L[6],a20=L[8],a21=L[9],a22=L[10];
    float det = a00*(a11*a22-a12*a21) - a01*(a10*a22-a12*a20) + a02*(a10*a21-a11*a20);
    float id = 1.f/det;
    float x = ((a11*a22-a12*a21)*cx + (a02*a21-a01*a22)*cy + (a01*a12-a02*a11)*cz)*id;
    float y = ((a12*a20-a10*a22)*cx + (a00*a22-a02*a20)*cy + (a02*a10-a00*a12)*cz)*id;
    float z = ((a10*a21-a11*a20)*cx + (a01*a20-a00*a21)*cy + (a00*a11-a01*a10)*cz)*id;
    const float* P = l2i + (b*NCC + c)*16;
    float px = P[0]*x + P[1]*y + P[2]*z  + P[3];
    float py = P[4]*x + P[5]*y + P[6]*z  + P[7];
    float pz = P[8]*x + P[9]*y + P[10]*z + P[11];
    float zz = fminf(fmaxf(pz, 1e-5f), 100000.f);
    float qx = px/zz, qy = py/zz;
    const float* A = aug + (b*NCC + c)*16;
    float ux = A[0]*qx + A[1]*qy + A[2]*zz + A[3];
    float uy = A[4]*qx + A[5]*qy + A[6]*zz + A[7];
    int on = (uy < (float)IMG_H) && (uy >= 0.f) && (ux < (float)IMG_W) && (ux >= 0.f);
    g_theta[t*6+0]=r[0]; g_theta[t*6+1]=r[1]; g_theta[t*6+2]=ux/(float)IMG_W*2.f-1.f;
    g_theta[t*6+3]=r[2]; g_theta[t*6+4]=r[3]; g_theta[t*6+5]=uy/(float)IMG_H*2.f-1.f;
    g_valid[t] = on;
}

// ---------------- grid sample -> padded half crops ----------------
__global__ void sample_kernel(const float* __restrict__ imgs)
{
    long long idx = (long long)blockIdx.x*blockDim.x + threadIdx.x;
    if (idx >= (long long)NIMG*CROPS*CROPS) return;
    int x = (int)(idx % CROPS);
    int y = (int)((idx / CROPS) % CROPS);
    int ii = (int)(idx / (CROPS*CROPS));
    int c = ii % NCC; int n = ii / NCC; int b = n / NBB;
    float t0 = g_theta[ii*6+0], t1 = g_theta[ii*6+1], t2 = g_theta[ii*6+2];
    float t3 = g_theta[ii*6+3], t4 = g_theta[ii*6+4], t5 = g_theta[ii*6+5];
    float gx = (2.f*x + 1.f)/(float)CROPS - 1.f;
    float gy = (2.f*y + 1.f)/(float)CROPS - 1.f;
    float g0 = gx*t0 + gy*t1 + t2;
    float g1 = gx*t3 + gy*t4 + t5;
    float ixf = ((g0 + 1.f)*(float)IMG_W - 1.f)*0.5f;
    float iyf = ((g1 + 1.f)*(float)IMG_H - 1.f)*0.5f;
    float x0 = floorf(ixf), y0 = floorf(iyf);
    float wx = ixf - x0, wy = iyf - y0;
    float x1 = x0 + 1.f, y1 = y0 + 1.f;
    bool vx0 = (x0 >= 0.f) && (x0 <= (float)(IMG_W-1));
    bool vx1 = (x1 >= 0.f) && (x1 <= (float)(IMG_W-1));
    bool vy0 = (y0 >= 0.f) && (y0 <= (float)(IMG_H-1));
    bool vy1 = (y1 >= 0.f) && (y1 <= (float)(IMG_H-1));
    int xi0 = (int)fminf(fmaxf(x0,0.f),(float)(IMG_W-1));
    int xi1 = (int)fminf(fmaxf(x1,0.f),(float)(IMG_W-1));
    int yi0 = (int)fminf(fmaxf(y0,0.f),(float)(IMG_H-1));
    int yi1 = (int)fminf(fmaxf(y1,0.f),(float)(IMG_H-1));
    float w00=(1.f-wx)*(1.f-wy), w01=wx*(1.f-wy), w10=(1.f-wx)*wy, w11=wx*wy;
    const float* base = imgs + (long long)(b*NCC + c)*3LL*IMG_H*IMG_W;
    #pragma unroll
    for (int ch = 0; ch < 3; ch++) {
        const float* im = base + (long long)ch*IMG_H*IMG_W;
        float v00 = (vx0&&vy0) ? im[yi0*IMG_W + xi0] : 0.f;
        float v01 = (vx1&&vy0) ? im[yi0*IMG_W + xi1] : 0.f;
        float v10 = (vx0&&vy1) ? im[yi1*IMG_W + xi0] : 0.f;
        float v11 = (vx1&&vy1) ? im[yi1*IMG_W + xi1] : 0.f;
        g_cropsp[(long long)ch*CP_CH + (long long)ii*CP_IMG + (y+1)*CP_PW + (x+1)] =
            __float2half_rn(v00*w00 + v01*w01 + v10*w10 + v11*w11);
    }
}

// ---------------- cp.async helpers ----------------
__device__ __forceinline__ void cpasync16(unsigned dst, const void* src) {
    asm volatile("cp.async.cg.shared.global [%0], [%1], 16;\n"
        :: "r"(dst), "l"(src) : "memory");
}
#define CP_COMMIT() asm volatile("cp.async.commit_group;\n" ::: "memory")
#define CP_WAIT1()  asm volatile("cp.async.wait_group 1;\n" ::: "memory")

// =====================================================================
// Half-native pipelined GEMM, m16n8k16 fp16 MMA, fp32 accum.
// CW: 0=float C, 1=half C, 2=packed-dense-B C, 3=scatter to h2p,
//     4=float C TRANSPOSED via smem staging (h3T[n][m], coalesced)
// =====================================================================
template<int LOADER, int BM, bool RELU, int CW>
__global__ __launch_bounds__(256) void hgemm(
    const unsigned* __restrict__ A, const void* __restrict__ Bp, void* __restrict__ Cp,
    int Kpad, int N, int ldc)
{
    constexpr int SROW = BM + 8;
    constexpr int ASZ  = 16*SROW;
    constexpr int BSZ  = 16*136;
    extern __shared__ unsigned smemU[];
    int2* sTab = (int2*)(smemU + 3*(ASZ+BSZ));

    const int tid = threadIdx.x;
    const int bx = blockIdx.x, by = blockIdx.y;
    const int lane = tid & 31, warp = tid >> 5;
    const int g = lane >> 2, tg = lane & 3;
    constexpr int WMC = BM/32;
    constexpr int WN  = 128/(8/WMC);
    constexpr int NT  = WN/8;
    const int wm = (warp % WMC)*32;
    const int wn = (warp / WMC)*WN;

    const int NCH = Kpad/32;
    const int T = NCH;

    const int nloc = tid & 127;
    const int ngl  = bx*128 + nloc;
    const int hsel = tid >> 7;
    const __half* Bh = (const __half*)Bp;
    const unsigned* Bu = (const unsigned*)Bp;

    const __half* Bbase = Bh;
    if (LOADER == 1) {
        int img = ngl/3136, pos = ngl - img*3136;
        int oy = pos/56, ox = pos - oy*56;
        Bbase = Bh + ((long long)img*CP_IMG + oy*4*CP_PW + ox*4);
    } else if (LOADER == 2) {
        int img = ngl/196, pos = ngl - img*196;
        int oy = pos/14, ox = pos - oy*14;
        Bbase = Bh + ((long long)img*3136 + oy*4*56 + ox*4);
    } else if (LOADER == 3) {
        int img = ngl/49, pos = ngl - img*49;
        int oy = pos/7, ox = pos - oy*7;
        Bbase = Bh + ((long long)img*H2P_IMG + oy*2*15 + ox*2);
    }

    if (LOADER != 0) {
        int TPK = Kpad/2;
        for (int kp = tid; kp < TPK; kp += 256) {
            int2 e;
            #pragma unroll
            for (int h = 0; h < 2; h++) {
                int k = kp*2 + h;
                int D = 0;
                if (LOADER == 1) {
                    if (k < K1) {
                        int ch = k/49, rr = k - ch*49;
                        int ky = rr/7, kx = rr - ky*7;
                        D = ch*CP_CH + ky*CP_PW + kx;
                    }
                } else if (LOADER == 2) {
                    int ic = k/9, rr = k - ic*9;
                    int ky = rr/3, kx = rr - ky*3;
                    D = ic*(int)N1 + ky*56 + kx;
                } else if (LOADER == 3) {
                    int ic = k/9, rr = k - ic*9;
                    int ky = rr/3, kx = rr - ky*3;
                    D = ic*H2P_IC + ky*15 + kx;
                }
                if (h == 0) e.x = D; else e.y = D;
            }
            sTab[kp] = e;
        }
        __syncthreads();
    }

    unsigned sbase = (unsigned)__cvta_generic_to_shared(smemU);

    unsigned Breg[8];
    auto gatherB = [&](int chunk) {
        #pragma unroll
        for (int j = 0; j < 8; j++) {
            int2 dd = sTab[chunk*16 + hsel*8 + j];
            unsigned v0 = (unsigned)__half_as_ushort(Bbase[dd.x]);
            unsigned v1 = (unsigned)__half_as_ushort(Bbase[dd.y]);
            Breg[j] = v0 | (v1 << 16);
        }
    };
    auto storeB = [&](int st) {
        unsigned* sB = smemU + st*(ASZ+BSZ) + ASZ;
        #pragma unroll
        for (int j = 0; j < 8; j++)
            sB[(hsel*8 + j)*136 + nloc] = Breg[j];
    };
    auto loadA_cp = [&](int st, int chunk) {
        unsigned sa = sbase + (unsigned)(st*(ASZ+BSZ)*4);
        constexpr int perkp = BM/4;
        constexpr int NTR = 16*perkp;
        #pragma unroll
        for (int i = 0; i < NTR/256; i++) {
            int e = tid + i*256;
            int kp = e / perkp, mq = (e % perkp)*4;
            const unsigned* src = A + ((long long)(by*NCH + chunk)*16 + kp)*BM + mq;
            cpasync16(sa + (unsigned)((kp*SROW + mq)*4), src);
        }
    };
    auto loadB_cp = [&](int st, int chunk) {
        unsigned sb = sbase + (unsigned)((st*(ASZ+BSZ) + ASZ)*4);
        #pragma unroll
        for (int i = 0; i < 2; i++) {
            int e = tid + i*256;
            int kp = e >> 5, nq = (e & 31)*4;
            const unsigned* src = Bu + (long long)(chunk*16 + kp)*N + bx*128 + nq;
            cpasync16(sb + (unsigned)((kp*136 + nq)*4), src);
        }
    };

    float acc[2][NT][4];
    #pragma unroll
    for (int i=0;i<2;i++)
        #pragma unroll
        for (int j=0;j<NT;j++)
            #pragma unroll
            for (int q=0;q<4;q++) acc[i][j][q] = 0.f;

    if (LOADER == 0) {
        loadA_cp(0,0); loadB_cp(0,0); CP_COMMIT();
        loadA_cp(1,1); loadB_cp(1,1); CP_COMMIT();
    } else {
        gatherB(0); storeB(0);
        gatherB(1);
        loadA_cp(0,0); CP_COMMIT();
        loadA_cp(1,1); CP_COMMIT();
    }

    for (int kt = 0; kt < T; kt++) {
        CP_WAIT1();
        __syncthreads();
        int kn = kt + 2;
        if (kn < T) {
            int stn = kn % 3;
            loadA_cp(stn, kn);
            if (LOADER == 0) loadB_cp(stn, kn);
        }
        CP_COMMIT();

        int st = kt % 3;
        const unsigned* sA = smemU + st*(ASZ+BSZ);
        const unsigned* sB = sA + ASZ;
        #pragma unroll
        for (int s = 0; s < 2; s++) {
            int kb = s*8;
            unsigned af[2][4];
            #pragma unroll
            for (int mt = 0; mt < 2; mt++) {
                int r1 = wm + mt*16 + g;
                af[mt][0] = sA[(kb+tg)*SROW + r1];
                af[mt][1] = sA[(kb+tg)*SROW + r1 + 8];
                af[mt][2] = sA[(kb+tg+4)*SROW + r1];
                af[mt][3] = sA[(kb+tg+4)*SROW + r1 + 8];
            }
            unsigned bf[NT][2];
            #pragma unroll
            for (int nt = 0; nt < NT; nt++) {
                int cc = wn + nt*8 + g;
                bf[nt][0] = sB[(kb+tg)*136 + cc];
                bf[nt][1] = sB[(kb+tg+4)*136 + cc];
            }
            #pragma unroll
            for (int mt = 0; mt < 2; mt++)
                #pragma unroll
                for (int nt = 0; nt < NT; nt++) {
                    asm volatile(
                        "mma.sync.aligned.m16n8k16.row.col.f32.f16.f16.f32 "
                        "{%0,%1,%2,%3}, {%4,%5,%6,%7}, {%8,%9}, {%0,%1,%2,%3};\n"
                        : "+f"(acc[mt][nt][0]), "+f"(acc[mt][nt][1]),
                          "+f"(acc[mt][nt][2]), "+f"(acc[mt][nt][3])
                        : "r"(af[mt][0]), "r"(af[mt][1]), "r"(af[mt][2]), "r"(af[mt][3]),
                          "r"(bf[nt][0]), "r"(bf[nt][1]));
                }
        }
        if (LOADER != 0) {
            if (kt+1 < T) storeB((kt+1) % 3);
            if (kt+2 < T) gatherB(kt+2);
        }
    }

    if (CW == 4) {
        // transposed float epilogue via smem staging: C[n*ldc + m], coalesced in m
        float* C = (float*)Cp;
        float* sbuf = (float*)smemU;
        #pragma unroll
        for (int pass = 0; pass < 2; pass++) {
            __syncthreads();
            #pragma unroll
            for (int mt = 0; mt < 2; mt++) {
                int r0 = wm + mt*16 + g;
                #pragma unroll
                for (int nt = 0; nt < NT; nt++) {
                    int cc = wn + nt*8 + tg*2;
                    float v0 = acc[mt][nt][0], v1 = acc[mt][nt][1];
                    float v2 = acc[mt][nt][2], v3 = acc[mt][nt][3];
                    if (RELU) { v0=fmaxf(v0,0.f); v1=fmaxf(v1,0.f); v2=fmaxf(v2,0.f); v3=fmaxf(v3,0.f); }
                    if ((r0 >> 6) == pass) {
                        int rr = r0 & 63;
                        sbuf[rr*133 + cc] = v0; sbuf[rr*133 + cc + 1] = v1;
                    }
                    if (((r0+8) >> 6) == pass) {
                        int rr = (r0+8) & 63;
                        sbuf[rr*133 + cc] = v2; sbuf[rr*133 + cc + 1] = v3;
                    }
                }
            }
            __syncthreads();
            #pragma unroll
            for (int it = 0; it < 32; it++) {
                int e = it*256 + tid;
                int cc = e >> 6, rr = e & 63;
                int m = by*128 + pass*64 + rr;
                int n = bx*128 + cc;
                C[(long long)n*ldc + m] = sbuf[rr*133 + cc];
            }
        }
        return;
    }

    #pragma unroll
    for (int mt = 0; mt < 2; mt++) {
        int r0 = by*BM + wm + mt*16 + g;
        #pragma unroll
        for (int nt = 0; nt < NT; nt++) {
            int c0 = bx*128 + wn + nt*8 + tg*2;
            float v0 = acc[mt][nt][0], v1 = acc[mt][nt][1];
            float v2 = acc[mt][nt][2], v3 = acc[mt][nt][3];
            if (RELU) { v0=fmaxf(v0,0.f); v1=fmaxf(v1,0.f); v2=fmaxf(v2,0.f); v3=fmaxf(v3,0.f); }
            if (CW == 0) {
                float* C = (float*)Cp;
                *reinterpret_cast<float2*>(C + (long long)r0*ldc + c0)     = make_float2(v0, v1);
                *reinterpret_cast<float2*>(C + (long long)(r0+8)*ldc + c0) = make_float2(v2, v3);
            } else if (CW == 1) {
                __half* C = (__half*)Cp;
                __half2 h0 = __floats2half2_rn(v0, v1);
                __half2 h1 = __floats2half2_rn(v2, v3);
                *reinterpret_cast<__half2*>(C + (long long)r0*ldc + c0)     = h0;
                *reinterpret_cast<__half2*>(C + (long long)(r0+8)*ldc + c0) = h1;
            } else if (CW == 2) {
                __half* C = (__half*)Cp;
                auto st1 = [&](int r, int c, float v) {
                    long long idx = ((long long)((r>>5)*16 + ((r>>1)&15))*N + c)*2 + (r&1);
                    C[idx] = __float2half_rn(v);
                };
                st1(r0,   c0,   v0); st1(r0,   c0+1, v1);
                st1(r0+8, c0,   v2); st1(r0+8, c0+1, v3);
            } else {  // CW==3: scatter to padded h2p
                __half* C = (__half*)Cp;
                auto st2 = [&](int r, int c, float v) {
                    int img = c/196; int pos = c - img*196;
                    int oy = pos/14, ox = pos - oy*14;
                    C[(long long)r*H2P_IC + img*H2P_IMG + oy*15 + ox] = __float2half_rn(v);
                };
                st2(r0,   c0,   v0); st2(r0,   c0+1, v1);
                st2(r0+8, c0,   v2); st2(r0+8, c0+1, v3);
            }
        }
    }
}

// ---------------- tokens (coalesced h3T reads) ----------------
__global__ void tok_kernel(const float* __restrict__ pos_embed)
{
    int i = blockIdx.x;
    int mblk = i >> 7, mloc = i & 127;
    __half* tp = (__half*)g_tok0p;
    for (int d = threadIdx.x; d < DIMK; d += blockDim.x) {
        float s = 0.f;
        #pragma unroll 7
        for (int p = 0; p < 49; p++) {
            float v = g_h3T[(long long)(i*49 + p)*1024 + d];
            s += v;
            g_tok[((long long)i*50 + 1 + p)*DIMK + d] = v + pos_embed[(1+p)*DIMK + d];
        }
        float t0 = s*(1.f/49.f) + pos_embed[d];
        g_tok[(long long)i*50*DIMK + d] = t0;
        int chunk = d >> 5, kp = (d & 31) >> 1;
        tp[(((long long)(mblk*32 + chunk)*16 + kp)*128 + mloc)*2 + (d&1)] = __float2half_rn(t0);
    }
}

// ---------------- attention ----------------
__global__ void attn_kernel()
{
    int i = blockIdx.x;
    __shared__ float sS[DIMK];
    __shared__ float slog[64];
    const float* t = g_tok + (long long)i*50*DIMK;
    for (int d = threadIdx.x; d < DIMK; d += blockDim.x) sS[d] = g_S[i*DIMK + d];
    __syncthreads();
    int w = threadIdx.x >> 5, lane = threadIdx.x & 31;
    for (int j = w; j < 50; j += 8) {
        const float* tj = t + (long long)j*DIMK;
        float s = 0.f;
        for (int d = lane; d < DIMK; d += 32) s += sS[d]*tj[d];
        #pragma unroll
        for (int o = 16; o > 0; o >>= 1) s += __shfl_down_sync(0xffffffff, s, o);
        if (lane == 0) slog[j] = s * 0.03125f;
    }
    __syncthreads();
    if (threadIdx.x == 0) {
        float mx = slog[0];
        for (int j = 1; j < 50; j++) mx = fmaxf(mx, slog[j]);
        float sum = 0.f;
        for (int j = 0; j < 50; j++) { float e = expf(slog[j]-mx); slog[j]=e; sum+=e; }
        float inv = 1.f/sum;
        for (int j = 0; j < 50; j++) slog[j] *= inv;
    }
    __syncthreads();
    int mblk = i >> 7, mloc = i & 127;
    __half* cp = (__half*)g_CTXp;
    for (int d = threadIdx.x; d < DIMK; d += blockDim.x) {
        float c = 0.f;
        #pragma unroll 10
        for (int j = 0; j < 50; j++) c += slog[j]*t[(long long)j*DIMK + d];
        int chunk = d >> 5, kp = (d & 31) >> 1;
        cp[(((long long)(mblk*32 + chunk)*16 + kp)*128 + mloc)*2 + (d&1)] = __float2half_rn(c);
    }
}

// ---------------- final EMA fuse ----------------
__global__ void fuse_kernel(const float* __restrict__ bdd,
                            const float* __restrict__ momentum,
                            float* __restrict__ out)
{
    int n = blockIdx.x;
    float mom = *momentum;
    const int order[6] = {2,0,1,5,3,4};
    for (int d = threadIdx.x; d < DIMK; d += blockDim.x) {
        float e = bdd[d];
        #pragma unroll
        for (int k = 0; k < 6; k++) {
            int c = order[k];
            int ii = n*NCC + c;
            if (g_valid[ii]) e = mom*e + (1.f - mom)*g_EMB[(long long)ii*DIMK + d];
        }
        out[n*DIMK + d] = e;
    }
}

// ---------------- launch ----------------
static inline void* symv(const void* s) {
    void* p = nullptr; cudaGetSymbolAddress(&p, s); return p;
}
#define ABSZ128 ((16*(128+8) + 16*136)*4)
#define ABSZ64  ((16*(64+8)  + 16*136)*4)
#define SMEM_D   (3*ABSZ128)
#define SMEM_C1  (3*ABSZ64  + 80*8)
#define SMEM_C2  (3*ABSZ128 + 288*8)
#define SMEM_C3  (3*ABSZ128 + 1152*8)

extern "C" void kernel_launch(void* const* d_in, const int* in_sizes, int n_in,
                              void* d_out, int out_size)
{
    const float* camera_imgs = (const float*)d_in[0];
    const float* pred_boxes  = (const float*)d_in[1];
    const float* img_aug     = (const float*)d_in[2];
    const float* lidar_aug   = (const float*)d_in[3];
    const float* lidar2img   = (const float*)d_in[4];
    const float* momentum    = (const float*)d_in[5];
    const float* bdd         = (const float*)d_in[6];
    const float* theta_w     = (const float*)d_in[7];
    const float* theta_b     = (const float*)d_in[8];
    const float* conv1       = (const float*)d_in[9];
    const float* conv2       = (const float*)d_in[10];
    const float* conv3       = (const float*)d_in[11];
    const float* pos_embed   = (const float*)d_in[12];
    const float* wq          = (const float*)d_in[13];
    const float* wk          = (const float*)d_in[14];
    const float* wv          = (const float*)d_in[15];
    const float* wo          = (const float*)d_in[16];
    float* out = (float*)d_out;

    unsigned* pwqp = (unsigned*)symv(g_wqp);
    unsigned* pwvp = (unsigned*)symv(g_wvp);
    unsigned* pwkT = (unsigned*)symv(g_wkTp);
    unsigned* pwop = (unsigned*)symv(g_wop);
    unsigned* pMp  = (unsigned*)symv(g_Mp);
    unsigned* pWvop= (unsigned*)symv(g_Wvop);
    unsigned* pw1  = (unsigned*)symv(g_w1p);
    unsigned* pw2  = (unsigned*)symv(g_w2p);
    unsigned* pw3  = (unsigned*)symv(g_w3p);
    unsigned* ptok0= (unsigned*)symv(g_tok0p);
    unsigned* pCTX = (unsigned*)symv(g_CTXp);
    __half* pcropsp= (__half*)symv(g_cropsp);
    __half* ph1    = (__half*)symv(g_h1h);
    __half* ph2p   = (__half*)symv(g_h2p);
    float*  ph3T   = (float*)symv(g_h3T);
    float*  pS     = (float*)symv(g_S);
    float*  pEMB   = (float*)symv(g_EMB);

    cudaFuncSetAttribute(hgemm<0,128,false,2>, cudaFuncAttributeMaxDynamicSharedMemorySize, SMEM_D);
    cudaFuncSetAttribute(hgemm<0,128,false,0>, cudaFuncAttributeMaxDynamicSharedMemorySize, SMEM_D);
    cudaFuncSetAttribute(hgemm<1,64, true, 1>, cudaFuncAttributeMaxDynamicSharedMemorySize, SMEM_C1);
    cudaFuncSetAttribute(hgemm<2,128,true, 3>, cudaFuncAttributeMaxDynamicSharedMemorySize, SMEM_C2);
    cudaFuncSetAttribute(hgemm<3,128,true, 4>, cudaFuncAttributeMaxDynamicSharedMemorySize, SMEM_C3);

    // ---- halo zeros (replaces full-buffer zero fills) ----
    haloc_kernel<<<3*NIMG,256>>>();
    haloh2_kernel<<<(unsigned)((256LL*NIMG*29 + 255)/256),256>>>();

    // ---- pack weights (single stream, R8 schedule) ----
    packA_kernel<<<2048,256>>>(wq, pwqp, 1024, 1024, 128, 1024, 512LL*1024);
    packA_kernel<<<2048,256>>>(wv, pwvp, 1024, 1024, 128, 1024, 512LL*1024);
    packBd_kernel<<<2048,256>>>(wk, pwkT, 1024, 1024, 1);
    packBd_kernel<<<2048,256>>>(wo, pwop, 1024, 1024, 0);
    packA_kernel<<<20,256>>>(conv1, pw1, 64, K1, 64, 160, 64LL*80);
    packA_kernel<<<288,256>>>(conv2, pw2, 256, K2, 128, 576, 256LL*288);
    packA_kernel<<<4608,256>>>(conv3, pw3, 1024, K3, 128, 2304, 1024LL*1152);

    // ---- M = wq@wk^T ; Wvo = wv@wo ----
    hgemm<0,128,false,2><<<dim3(8,8),256,SMEM_D>>>(pwqp, pwkT, pMp, 1024, 1024, 1024);
    hgemm<0,128,false,2><<<dim3(8,8),256,SMEM_D>>>(pwvp, pwop, pWvop, 1024, 1024, 1024);

    theta_kernel<<<2,192>>>(pred_boxes, lidar_aug, lidar2img, img_aug, theta_w, theta_b);
    {
        long long total = (long long)NIMG*CROPS*CROPS;
        sample_kernel<<<(unsigned)((total+255)/256),256>>>(camera_imgs);
    }

    // conv1: M=64, Kpad=160, gather from padded crops
    hgemm<1,64,true,1><<<dim3((unsigned)(N1/128),1),256,SMEM_C1>>>(pw1, pcropsp, ph1, 160, 0, (int)N1);
    // conv2: M=256, K=576 -> scatter to padded h2p
    hgemm<2,128,true,3><<<dim3((unsigned)(N2/128),2),256,SMEM_C2>>>(pw2, ph1, ph2p, 576, 0, 0);
    // conv3: M=1024, K=2304 -> transposed float h3T [n][1024]
    hgemm<3,128,true,4><<<dim3((unsigned)(N3/128),8),256,SMEM_C3>>>(pw3, ph2p, ph3T, 2304, 0, 1024);

    tok_kernel<<<NIMG,256>>>(pos_embed);

    // S = tok0 @ M
    hgemm<0,128,false,0><<<dim3(8,3),256,SMEM_D>>>(ptok0, pMp, pS, 1024, 1024, DIMK);

    attn_kernel<<<NIMG,256>>>();

    // EMB = CTX @ Wvo
    hgemm<0,128,false,0><<<dim3(8,3),256,SMEM_D>>>(pCTX, pWvop, pEMB, 1024, 1024, DIMK);

    fuse_kernel<<<NBOX,256>>>(bdd, momentum, out);
}

// round 11
// speedup vs baseline: 1.1774x; 1.1774x over previous
#include <cuda_runtime.h>
#include <cuda_fp16.h>
#include <math.h>

#define DIMK   1024
#define IMG_H  512
#define IMG_W  1408
#define CROPS  224
#define NCC    6
#define NBB    32
#define NBOX   64
#define NIMG   384
#define O1 56
#define O2 14
#define O3 7
#define N1 ((long long)NIMG*O1*O1)   // 1204224
#define N2 ((long long)NIMG*O2*O2)   // 75264
#define N3 ((long long)NIMG*O3*O3)   // 18816
#define K1 147
#define K2 576
#define K3 2304
// padded crops: [ch][img][227][228]
#define CP_PW 228
#define CP_IMG (227*228)
#define CP_CH  (NIMG*CP_IMG)
// padded h2: [ic][img][15][15]
#define H2P_IMG 225
#define H2P_IC  (NIMG*H2P_IMG)

// ---------------- scratch ----------------
__device__ float  g_theta[NIMG*6];
__device__ int    g_valid[NIMG];
__device__ __align__(16) __half g_cropsp[3LL*CP_CH];
__device__ __half g_h1h[64LL*N1];
__device__ __align__(16) __half g_h2p[256LL*H2P_IC];
__device__ float  g_h3[1024LL*N3];               // [oc][n]  (R8 layout)
__device__ float  g_tok[(long long)NIMG*50*DIMK];
__device__ float  g_S[NIMG*DIMK];
__device__ float  g_EMB[NIMG*DIMK];
__device__ unsigned g_wqp[512*1024], g_wvp[512*1024];
__device__ unsigned g_wkTp[512*1024], g_wop[512*1024];
__device__ unsigned g_Mp[512*1024], g_Wvop[512*1024];
__device__ unsigned g_w1p[64*80];
__device__ unsigned g_w2p[256*288];
__device__ unsigned g_w3p[1024*1152];
__device__ unsigned g_tok0p[384*512];
__device__ unsigned g_CTXp[384*512];

// ---------------- halo zero kernels (proven bit-exact in R9/R10) ------------
__global__ void haloc_kernel()
{
    long long base = (long long)blockIdx.x*CP_IMG;   // blockIdx.x = ch*NIMG+img
    __half z = __ushort_as_half((unsigned short)0);
    for (int t = threadIdx.x; t < 3*CP_PW; t += 256) {
        int r = t/CP_PW, c = t - (t/CP_PW)*CP_PW;
        int row = (r == 0) ? 0 : (224 + r);          // rows 0,225,226
        g_cropsp[base + row*CP_PW + c] = z;
    }
    for (int t = threadIdx.x; t < 224*4; t += 256) {
        int row = 1 + (t >> 2); int c4 = t & 3;
        int col = (c4 == 0) ? 0 : (224 + c4);        // cols 0,225,226,227
        g_cropsp[base + row*CP_PW + col] = z;
    }
}
__global__ void haloh2_kernel()
{
    long long i = (long long)blockIdx.x*256 + threadIdx.x;
    if (i >= 256LL*NIMG*29) return;
    int e = (int)(i % 29); long long pair = i / 29;
    int off = (e < 15) ? (14*15 + e) : ((e - 15)*15 + 14);
    g_h2p[pair*225 + off] = __ushort_as_half((unsigned short)0);
}

// ---------------- pack kernels ----------------
__global__ void packA_kernel(const float* __restrict__ src, unsigned* __restrict__ dst,
                             int Ms, int Ks, int BMp, int Kpad, long long total)
{
    long long i = (long long)blockIdx.x*256 + threadIdx.x;
    if (i >= total) return;
    int NCH = Kpad/32;
    int mloc = (int)(i % BMp); long long r = i / BMp;
    int kp = (int)(r % 16); r /= 16;
    int chunk = (int)(r % NCH); int mblk = (int)(r / NCH);
    int m = mblk*BMp + mloc, k = chunk*32 + kp*2;
    float v0 = (m < Ms && k   < Ks) ? src[(long long)m*Ks + k]   : 0.f;
    float v1 = (m < Ms && k+1 < Ks) ? src[(long long)m*Ks + k+1] : 0.f;
    __half2 h = __floats2half2_rn(v0, v1);
    dst[i] = *reinterpret_cast<unsigned*>(&h);
}

// merged pack of wq(A-form), wv(A-form), wk(B-form,transposed), wo(B-form)
__global__ void packQKVO_kernel(const float* __restrict__ wq, const float* __restrict__ wv,
                                const float* __restrict__ wk, const float* __restrict__ wo,
                                unsigned* __restrict__ dq, unsigned* __restrict__ dv,
                                unsigned* __restrict__ dkT, unsigned* __restrict__ dwo)
{
    int sect = blockIdx.x >> 11;            // 4 sections x 2048 blocks
    long long i = (long long)(blockIdx.x & 2047)*256 + threadIdx.x;
    if (i >= 512LL*1024) return;
    float v0, v1;
    unsigned* dst;
    if (sect < 2) {
        // A-form: idx = ((mblk*32 + chunk)*16 + kp)*128 + mloc
        int mloc = (int)(i % 128); long long r = i / 128;
        int kp = (int)(r % 16); r /= 16;
        int chunk = (int)(r % 32); int mblk = (int)(r / 32);
        int m = mblk*128 + mloc, k = chunk*32 + kp*2;
        const float* s = (sect == 0) ? wq : wv;
        v0 = s[(long long)m*1024 + k]; v1 = s[(long long)m*1024 + k + 1];
        dst = (sect == 0) ? dq : dv;
    } else {
        // B-form: idx = (chunk*16+kp)*1024 + n
        int n = (int)(i % 1024); long long r = i / 1024;
        int kp = (int)(r % 16); int chunk = (int)(r / 16);
        int k = chunk*32 + kp*2;
        if (sect == 2) { v0 = wk[(long long)n*1024 + k];  v1 = wk[(long long)n*1024 + k + 1];  dst = dkT; }
        else           { v0 = wo[(long long)k*1024 + n];  v1 = wo[(long long)(k+1)*1024 + n];  dst = dwo; }
    }
    __half2 h = __floats2half2_rn(v0, v1);
    dst[i] = *reinterpret_cast<unsigned*>(&h);
}

// ---------------- theta ----------------
__global__ void theta_kernel(const float* __restrict__ boxes, const float* __restrict__ la,
                             const float* __restrict__ l2i, const float* __restrict__ aug,
                             const float* __restrict__ thw, const float* __restrict__ thb)
{
    int t = blockIdx.x*blockDim.x + threadIdx.x;
    if (t >= NIMG) return;
    int c = t % NCC; int n = t / NCC; int b = n / NBB; int nb = n % NBB;
    const float* bx = boxes + (b*NBB + nb)*9;
    float r[4];
    #pragma unroll
    for (int i = 0; i < 4; i++) {
        float s = thb[i];
        #pragma unroll
        for (int j = 0; j < 9; j++) s += bx[j]*thw[i*9+j];
        r[i] = tanhf(s);
    }
    const float* L = la + b*16;
    float cx = bx[0]-L[3], cy = bx[1]-L[7], cz = bx[2]-L[11];
    float a00=L[0],a01=L[1],a02=L[2],a10=L[4],a11=L[5],a12=L[6],a20=L[8],a21=L[9],a22=L[10];
    float det = a00*(a11*a22-a12*a21) - a01*(a10*a22-a12*a20) + a02*(a10*a21-a11*a20);
    float id = 1.f/det;
    float x = ((a11*a22-a12*a21)*cx + (a02*a21-a01*a22)*cy + (a01*a12-a02*a11)*cz)*id;
    float y = ((a12*a20-a10*a22)*cx + (a00*a22-a02*a20)*cy + (a02*a10-a00*a12)*cz)*id;
    float z = ((a10*a21-a11*a20)*cx + (a01*a20-a00*a21)*cy + (a00*a11-a01*a10)*cz)*id;
    const float* P = l2i + (b*NCC + c)*16;
    float px = P[0]*x + P[1]*y + P[2]*z  + P[3];
    float py = P[4]*x + P[5]*y + P[6]*z  + P[7];
    float pz = P[8]*x + P[9]*y + P[10]*z + P[11];
    float zz = fminf(fmaxf(pz, 1e-5f), 100000.f);
    float qx = px/zz, qy = py/zz;
    const float* A = aug + (b*NCC + c)*16;
    float ux = A[0]*qx + A[1]*qy + A[2]*zz + A[3];
    float uy = A[4]*qx + A[5]*qy + A[6]*zz + A[7];
    int on = (uy < (float)IMG_H) && (uy >= 0.f) && (ux < (float)IMG_W) && (ux >= 0.f);
    g_theta[t*6+0]=r[0]; g_theta[t*6+1]=r[1]; g_theta[t*6+2]=ux/(float)IMG_W*2.f-1.f;
    g_theta[t*6+3]=r[2]; g_theta[t*6+4]=r[3]; g_theta[t*6+5]=uy/(float)IMG_H*2.f-1.f;
    g_valid[t] = on;
}

// ---------------- grid sample -> padded half crops ----------------
__global__ void sample_kernel(const float* __restrict__ imgs)
{
    long long idx = (long long)blockIdx.x*blockDim.x + threadIdx.x;
    if (idx >= (long long)NIMG*CROPS*CROPS) return;
    int x = (int)(idx % CROPS);
    int y = (int)((idx / CROPS) % CROPS);
    int ii = (int)(idx / (CROPS*CROPS));
    int c = ii % NCC; int n = ii / NCC; int b = n / NBB;
    float t0 = g_theta[ii*6+0], t1 = g_theta[ii*6+1], t2 = g_theta[ii*6+2];
    float t3 = g_theta[ii*6+3], t4 = g_theta[ii*6+4], t5 = g_theta[ii*6+5];
    float gx = (2.f*x + 1.f)/(float)CROPS - 1.f;
    float gy = (2.f*y + 1.f)/(float)CROPS - 1.f;
    float g0 = gx*t0 + gy*t1 + t2;
    float g1 = gx*t3 + gy*t4 + t5;
    float ixf = ((g0 + 1.f)*(float)IMG_W - 1.f)*0.5f;
    float iyf = ((g1 + 1.f)*(float)IMG_H - 1.f)*0.5f;
    float x0 = floorf(ixf), y0 = floorf(iyf);
    float wx = ixf - x0, wy = iyf - y0;
    float x1 = x0 + 1.f, y1 = y0 + 1.f;
    bool vx0 = (x0 >= 0.f) && (x0 <= (float)(IMG_W-1));
    bool vx1 = (x1 >= 0.f) && (x1 <= (float)(IMG_W-1));
    bool vy0 = (y0 >= 0.f) && (y0 <= (float)(IMG_H-1));
    bool vy1 = (y1 >= 0.f) && (y1 <= (float)(IMG_H-1));
    int xi0 = (int)fminf(fmaxf(x0,0.f),(float)(IMG_W-1));
    int xi1 = (int)fminf(fmaxf(x1,0.f),(float)(IMG_W-1));
    int yi0 = (int)fminf(fmaxf(y0,0.f),(float)(IMG_H-1));
    int yi1 = (int)fminf(fmaxf(y1,0.f),(float)(IMG_H-1));
    float w00=(1.f-wx)*(1.f-wy), w01=wx*(1.f-wy), w10=(1.f-wx)*wy, w11=wx*wy;
    const float* base = imgs + (long long)(b*NCC + c)*3LL*IMG_H*IMG_W;
    #pragma unroll
    for (int ch = 0; ch < 3; ch++) {
        const float* im = base + (long long)ch*IMG_H*IMG_W;
        float v00 = (vx0&&vy0) ? im[yi0*IMG_W + xi0] : 0.f;
        float v01 = (vx1&&vy0) ? im[yi0*IMG_W + xi1] : 0.f;
        float v10 = (vx0&&vy1) ? im[yi1*IMG_W + xi0] : 0.f;
        float v11 = (vx1&&vy1) ? im[yi1*IMG_W + xi1] : 0.f;
        g_cropsp[(long long)ch*CP_CH + (long long)ii*CP_IMG + (y+1)*CP_PW + (x+1)] =
            __float2half_rn(v00*w00 + v01*w01 + v10*w10 + v11*w11);
    }
}

// ---------------- cp.async helpers ----------------
__device__ __forceinline__ void cpasync16(unsigned dst, const void* src) {
    asm volatile("cp.async.cg.shared.global [%0], [%1], 16;\n"
        :: "r"(dst), "l"(src) : "memory");
}
#define CP_COMMIT() asm volatile("cp.async.commit_group;\n" ::: "memory")
#define CP_WAIT1()  asm volatile("cp.async.wait_group 1;\n" ::: "memory")

// =====================================================================
// Half-native pipelined GEMM, m16n8k16 fp16 MMA, fp32 accum. (R8 core)
// Optional second problem via blockIdx.z==1 (Ax/Bpx/Cpx), same shape.
// CW: 0=float C, 1=half C, 2=packed-dense-B C, 3=scatter to h2p
// =====================================================================
template<int LOADER, int BM, bool RELU, int CW>
__global__ __launch_bounds__(256) void hgemm(
    const unsigned* __restrict__ A, const void* __restrict__ Bp, void* __restrict__ Cp,
    const unsigned* __restrict__ Ax, const void* __restrict__ Bpx, void* __restrict__ Cpx,
    int Kpad, int N, int ldc)
{
    if (blockIdx.z == 1) { A = Ax; Bp = Bpx; Cp = Cpx; }

    constexpr int SROW = BM + 8;
    constexpr int ASZ  = 16*SROW;
    constexpr int BSZ  = 16*136;
    extern __shared__ unsigned smemU[];
    int2* sTab = (int2*)(smemU + 3*(ASZ+BSZ));

    const int tid = threadIdx.x;
    const int bx = blockIdx.x, by = blockIdx.y;
    const int lane = tid & 31, warp = tid >> 5;
    const int g = lane >> 2, tg = lane & 3;
    constexpr int WMC = BM/32;
    constexpr int WN  = 128/(8/WMC);
    constexpr int NT  = WN/8;
    const int wm = (warp % WMC)*32;
    const int wn = (warp / WMC)*WN;

    const int NCH = Kpad/32;
    const int T = NCH;

    const int nloc = tid & 127;
    const int ngl  = bx*128 + nloc;
    const int hsel = tid >> 7;
    const __half* Bh = (const __half*)Bp;
    const unsigned* Bu = (const unsigned*)Bp;

    const __half* Bbase = Bh;
    if (LOADER == 1) {
        int img = ngl/3136, pos = ngl - img*3136;
        int oy = pos/56, ox = pos - oy*56;
        Bbase = Bh + ((long long)img*CP_IMG + oy*4*CP_PW + ox*4);
    } else if (LOADER == 2) {
        int img = ngl/196, pos = ngl - img*196;
        int oy = pos/14, ox = pos - oy*14;
        Bbase = Bh + ((long long)img*3136 + oy*4*56 + ox*4);
    } else if (LOADER == 3) {
        int img = ngl/49, pos = ngl - img*49;
        int oy = pos/7, ox = pos - oy*7;
        Bbase = Bh + ((long long)img*H2P_IMG + oy*2*15 + ox*2);
    }

    if (LOADER != 0) {
        int TPK = Kpad/2;
        for (int kp = tid; kp < TPK; kp += 256) {
            int2 e;
            #pragma unroll
            for (int h = 0; h < 2; h++) {
                int k = kp*2 + h;
                int D = 0;
                if (LOADER == 1) {
                    if (k < K1) {
                        int ch = k/49, rr = k - ch*49;
                        int ky = rr/7, kx = rr - ky*7;
                        D = ch*CP_CH + ky*CP_PW + kx;
                    }
                } else if (LOADER == 2) {
                    int ic = k/9, rr = k - ic*9;
                    int ky = rr/3, kx = rr - ky*3;
                    D = ic*(int)N1 + ky*56 + kx;
                } else if (LOADER == 3) {
                    int ic = k/9, rr = k - ic*9;
                    int ky = rr/3, kx = rr - ky*3;
                    D = ic*H2P_IC + ky*15 + kx;
                }
                if (h == 0) e.x = D; else e.y = D;
            }
            sTab[kp] = e;
        }
        __syncthreads();
    }

    unsigned sbase = (unsigned)__cvta_generic_to_shared(smemU);

    unsigned Breg[8];
    auto gatherB = [&](int chunk) {
        #pragma unroll
        for (int j = 0; j < 8; j++) {
            int2 dd = sTab[chunk*16 + hsel*8 + j];
            unsigned v0 = (unsigned)__half_as_ushort(Bbase[dd.x]);
            unsigned v1 = (unsigned)__half_as_ushort(Bbase[dd.y]);
            Breg[j] = v0 | (v1 << 16);
        }
    };
    auto storeB = [&](int st) {
        unsigned* sB = smemU + st*(ASZ+BSZ) + ASZ;
        #pragma unroll
        for (int j = 0; j < 8; j++)
            sB[(hsel*8 + j)*136 + nloc] = Breg[j];
    };
    auto loadA_cp = [&](int st, int chunk) {
        unsigned sa = sbase + (unsigned)(st*(ASZ+BSZ)*4);
        constexpr int perkp = BM/4;
        constexpr int NTR = 16*perkp;
        #pragma unroll
        for (int i = 0; i < NTR/256; i++) {
            int e = tid + i*256;
            int kp = e / perkp, mq = (e % perkp)*4;
            const unsigned* src = A + ((long long)(by*NCH + chunk)*16 + kp)*BM + mq;
            cpasync16(sa + (unsigned)((kp*SROW + mq)*4), src);
        }
    };
    auto loadB_cp = [&](int st, int chunk) {
        unsigned sb = sbase + (unsigned)((st*(ASZ+BSZ) + ASZ)*4);
        #pragma unroll
        for (int i = 0; i < 2; i++) {
            int e = tid + i*256;
            int kp = e >> 5, nq = (e & 31)*4;
            const unsigned* src = Bu + (long long)(chunk*16 + kp)*N + bx*128 + nq;
            cpasync16(sb + (unsigned)((kp*136 + nq)*4), src);
        }
    };

    float acc[2][NT][4];
    #pragma unroll
    for (int i=0;i<2;i++)
        #pragma unroll
        for (int j=0;j<NT;j++)
            #pragma unroll
            for (int q=0;q<4;q++) acc[i][j][q] = 0.f;

    if (LOADER == 0) {
        loadA_cp(0,0); loadB_cp(0,0); CP_COMMIT();
        loadA_cp(1,1); loadB_cp(1,1); CP_COMMIT();
    } else {
        gatherB(0); storeB(0);
        gatherB(1);
        loadA_cp(0,0); CP_COMMIT();
        loadA_cp(1,1); CP_COMMIT();
    }

    for (int kt = 0; kt < T; kt++) {
        CP_WAIT1();
        __syncthreads();
        int kn = kt + 2;
        if (kn < T) {
            int stn = kn % 3;
            loadA_cp(stn, kn);
            if (LOADER == 0) loadB_cp(stn, kn);
        }
        CP_COMMIT();

        int st = kt % 3;
        const unsigned* sA = smemU + st*(ASZ+BSZ);
        const unsigned* sB = sA + ASZ;
        #pragma unroll
        for (int s = 0; s < 2; s++) {
            int kb = s*8;
            unsigned af[2][4];
            #pragma unroll
            for (int mt = 0; mt < 2; mt++) {
                int r1 = wm + mt*16 + g;
                af[mt][0] = sA[(kb+tg)*SROW + r1];
                af[mt][1] = sA[(kb+tg)*SROW + r1 + 8];
                af[mt][2] = sA[(kb+tg+4)*SROW + r1];
                af[mt][3] = sA[(kb+tg+4)*SROW + r1 + 8];
            }
            unsigned bf[NT][2];
            #pragma unroll
            for (int nt = 0; nt < NT; nt++) {
                int cc = wn + nt*8 + g;
                bf[nt][0] = sB[(kb+tg)*136 + cc];
                bf[nt][1] = sB[(kb+tg+4)*136 + cc];
            }
            #pragma unroll
            for (int mt = 0; mt < 2; mt++)
                #pragma unroll
                for (int nt = 0; nt < NT; nt++) {
                    asm volatile(
                        "mma.sync.aligned.m16n8k16.row.col.f32.f16.f16.f32 "
                        "{%0,%1,%2,%3}, {%4,%5,%6,%7}, {%8,%9}, {%0,%1,%2,%3};\n"
                        : "+f"(acc[mt][nt][0]), "+f"(acc[mt][nt][1]),
                          "+f"(acc[mt][nt][2]), "+f"(acc[mt][nt][3])
                        : "r"(af[mt][0]), "r"(af[mt][1]), "r"(af[mt][2]), "r"(af[mt][3]),
                          "r"(bf[nt][0]), "r"(bf[nt][1]));
                }
        }
        if (LOADER != 0) {
            if (kt+1 < T) storeB((kt+1) % 3);
            if (kt+2 < T) gatherB(kt+2);
        }
    }

    #pragma unroll
    for (int mt = 0; mt < 2; mt++) {
        int r0 = by*BM + wm + mt*16 + g;
        #pragma unroll
        for (int nt = 0; nt < NT; nt++) {
            int c0 = bx*128 + wn + nt*8 + tg*2;
            float v0 = acc[mt][nt][0], v1 = acc[mt][nt][1];
            float v2 = acc[mt][nt][2], v3 = acc[mt][nt][3];
            if (RELU) { v0=fmaxf(v0,0.f); v1=fmaxf(v1,0.f); v2=fmaxf(v2,0.f); v3=fmaxf(v3,0.f); }
            if (CW == 0) {
                float* C = (float*)Cp;
                *reinterpret_cast<float2*>(C + (long long)r0*ldc + c0)     = make_float2(v0, v1);
                *reinterpret_cast<float2*>(C + (long long)(r0+8)*ldc + c0) = make_float2(v2, v3);
            } else if (CW == 1) {
                __half* C = (__half*)Cp;
                __half2 h0 = __floats2half2_rn(v0, v1);
                __half2 h1 = __floats2half2_rn(v2, v3);
                *reinterpret_cast<__half2*>(C + (long long)r0*ldc + c0)     = h0;
                *reinterpret_cast<__half2*>(C + (long long)(r0+8)*ldc + c0) = h1;
            } else if (CW == 2) {
                __half* C = (__half*)Cp;
                auto st1 = [&](int r, int c, float v) {
                    long long idx = ((long long)((r>>5)*16 + ((r>>1)&15))*N + c)*2 + (r&1);
                    C[idx] = __float2half_rn(v);
                };
                st1(r0,   c0,   v0); st1(r0,   c0+1, v1);
                st1(r0+8, c0,   v2); st1(r0+8, c0+1, v3);
            } else {  // CW==3: scatter to padded h2p
                __half* C = (__half*)Cp;
                auto st2 = [&](int r, int c, float v) {
                    int img = c/196; int pos = c - img*196;
                    int oy = pos/14, ox = pos - oy*14;
                    C[(long long)r*H2P_IC + img*H2P_IMG + oy*15 + ox] = __float2half_rn(v);
                };
                st2(r0,   c0,   v0); st2(r0,   c0+1, v1);
                st2(r0+8, c0,   v2); st2(r0+8, c0+1, v3);
            }
        }
    }
}

// ---------------- tokens (R8 version: per-thread h3 row streaming) ----------
__global__ void tok_kernel(const float* __restrict__ pos_embed)
{
    int i = blockIdx.x;
    int mblk = i >> 7, mloc = i & 127;
    __half* tp = (__half*)g_tok0p;
    for (int d = threadIdx.x; d < DIMK; d += blockDim.x) {
        const float* hp = g_h3 + (long long)d*N3 + (long long)i*49;
        float s = 0.f;
        #pragma unroll 7
        for (int p = 0; p < 49; p++) {
            float v = hp[p];
            s += v;
            g_tok[((long long)i*50 + 1 + p)*DIMK + d] = v + pos_embed[(1+p)*DIMK + d];
        }
        float t0 = s*(1.f/49.f) + pos_embed[d];
        g_tok[(long long)i*50*DIMK + d] = t0;
        int chunk = d >> 5, kp = (d & 31) >> 1;
        tp[(((long long)(mblk*32 + chunk)*16 + kp)*128 + mloc)*2 + (d&1)] = __float2half_rn(t0);
    }
}

// ---------------- attention ----------------
__global__ void attn_kernel()
{
    int i = blockIdx.x;
    __shared__ float sS[DIMK];
    __shared__ float slog[64];
    const float* t = g_tok + (long long)i*50*DIMK;
    for (int d = threadIdx.x; d < DIMK; d += blockDim.x) sS[d] = g_S[i*DIMK + d];
    __syncthreads();
    int w = threadIdx.x >> 5, lane = threadIdx.x & 31;
    for (int j = w; j < 50; j += 8) {
        const float* tj = t + (long long)j*DIMK;
        float s = 0.f;
        for (int d = lane; d < DIMK; d += 32) s += sS[d]*tj[d];
        #pragma unroll
        for (int o = 16; o > 0; o >>= 1) s += __shfl_down_sync(0xffffffff, s, o);
        if (lane == 0) slog[j] = s * 0.03125f;
    }
    __syncthreads();
    if (threadIdx.x == 0) {
        float mx = slog[0];
        for (int j = 1; j < 50; j++) mx = fmaxf(mx, slog[j]);
        float sum = 0.f;
        for (int j = 0; j < 50; j++) { float e = expf(slog[j]-mx); slog[j]=e; sum+=e; }
        float inv = 1.f/sum;
        for (int j = 0; j < 50; j++) slog[j] *= inv;
    }
    __syncthreads();
    int mblk = i >> 7, mloc = i & 127;
    __half* cp = (__half*)g_CTXp;
    for (int d = threadIdx.x; d < DIMK; d += blockDim.x) {
        float c = 0.f;
        #pragma unroll 10
        for (int j = 0; j < 50; j++) c += slog[j]*t[(long long)j*DIMK + d];
        int chunk = d >> 5, kp = (d & 31) >> 1;
        cp[(((long long)(mblk*32 + chunk)*16 + kp)*128 + mloc)*2 + (d&1)] = __float2half_rn(c);
    }
}

// ---------------- final EMA fuse ----------------
__global__ void fuse_kernel(const float* __restrict__ bdd,
                            const float* __restrict__ momentum,
                            float* __restrict__ out)
{
    int n = blockIdx.x;
    float mom = *momentum;
    const int order[6] = {2,0,1,5,3,4};
    for (int d = threadIdx.x; d < DIMK; d += blockDim.x) {
        float e = bdd[d];
        #pragma unroll
        for (int k = 0; k < 6; k++) {
            int c = order[k];
            int ii = n*NCC + c;
            if (g_valid[ii]) e = mom*e + (1.f - mom)*g_EMB[(long long)ii*DIMK + d];
        }
        out[n*DIMK + d] = e;
    }
}

// ---------------- launch ----------------
static inline void* symv(const void* s) {
    void* p = nullptr; cudaGetSymbolAddress(&p, s); return p;
}
#define ABSZ128 ((16*(128+8) + 16*136)*4)
#define ABSZ64  ((16*(64+8)  + 16*136)*4)
#define SMEM_D   (3*ABSZ128)
#define SMEM_C1  (3*ABSZ64  + 80*8)
#define SMEM_C2  (3*ABSZ128 + 288*8)
#define SMEM_C3  (3*ABSZ128 + 1152*8)

extern "C" void kernel_launch(void* const* d_in, const int* in_sizes, int n_in,
                              void* d_out, int out_size)
{
    const float* camera_imgs = (const float*)d_in[0];
    const float* pred_boxes  = (const float*)d_in[1];
    const float* img_aug     = (const float*)d_in[2];
    const float* lidar_aug   = (const float*)d_in[3];
    const float* lidar2img   = (const float*)d_in[4];
    const float* momentum    = (const float*)d_in[5];
    const float* bdd         = (const float*)d_in[6];
    const float* theta_w     = (const float*)d_in[7];
    const float* theta_b     = (const float*)d_in[8];
    const float* conv1       = (const float*)d_in[9];
    const float* conv2       = (const float*)d_in[10];
    const float* conv3       = (const float*)d_in[11];
    const float* pos_embed   = (const float*)d_in[12];
    const float* wq          = (const float*)d_in[13];
    const float* wk          = (const float*)d_in[14];
    const float* wv          = (const float*)d_in[15];
    const float* wo          = (const float*)d_in[16];
    float* out = (float*)d_out;

    unsigned* pwqp = (unsigned*)symv(g_wqp);
    unsigned* pwvp = (unsigned*)symv(g_wvp);
    unsigned* pwkT = (unsigned*)symv(g_wkTp);
    unsigned* pwop = (unsigned*)symv(g_wop);
    unsigned* pMp  = (unsigned*)symv(g_Mp);
    unsigned* pWvop= (unsigned*)symv(g_Wvop);
    unsigned* pw1  = (unsigned*)symv(g_w1p);
    unsigned* pw2  = (unsigned*)symv(g_w2p);
    unsigned* pw3  = (unsigned*)symv(g_w3p);
    unsigned* ptok0= (unsigned*)symv(g_tok0p);
    unsigned* pCTX = (unsigned*)symv(g_CTXp);
    __half* pcropsp= (__half*)symv(g_cropsp);
    __half* ph1    = (__half*)symv(g_h1h);
    __half* ph2p   = (__half*)symv(g_h2p);
    float*  ph3    = (float*)symv(g_h3);
    float*  pS     = (float*)symv(g_S);
    float*  pEMB   = (float*)symv(g_EMB);

    cudaFuncSetAttribute(hgemm<0,128,false,2>, cudaFuncAttributeMaxDynamicSharedMemorySize, SMEM_D);
    cudaFuncSetAttribute(hgemm<0,128,false,0>, cudaFuncAttributeMaxDynamicSharedMemorySize, SMEM_D);
    cudaFuncSetAttribute(hgemm<1,64, true, 1>, cudaFuncAttributeMaxDynamicSharedMemorySize, SMEM_C1);
    cudaFuncSetAttribute(hgemm<2,128,true, 3>, cudaFuncAttributeMaxDynamicSharedMemorySize, SMEM_C2);
    cudaFuncSetAttribute(hgemm<3,128,true, 0>, cudaFuncAttributeMaxDynamicSharedMemorySize, SMEM_C3);

    // ---- halo zeros (replaces full-buffer zero fills; bit-exact per R9/R10) ----
    haloc_kernel<<<3*NIMG,256>>>();
    haloh2_kernel<<<(unsigned)((256LL*NIMG*29 + 255)/256),256>>>();

    // ---- pack weights: qkvo merged into one launch; conv packs separate ----
    packQKVO_kernel<<<4*2048,256>>>(wq, wv, wk, wo, pwqp, pwvp, pwkT, pwop);
    packA_kernel<<<20,256>>>(conv1, pw1, 64, K1, 64, 160, 64LL*80);
    packA_kernel<<<288,256>>>(conv2, pw2, 256, K2, 128, 576, 256LL*288);
    packA_kernel<<<4608,256>>>(conv3, pw3, 1024, K3, 128, 2304, 1024LL*1152);

    // ---- M = wq@wk^T ; Wvo = wv@wo : merged via gridDim.z = 2 ----
    hgemm<0,128,false,2><<<dim3(8,8,2),256,SMEM_D>>>(
        pwqp, pwkT, pMp, pwvp, pwop, pWvop, 1024, 1024, 1024);

    theta_kernel<<<2,192>>>(pred_boxes, lidar_aug, lidar2img, img_aug, theta_w, theta_b);
    {
        long long total = (long long)NIMG*CROPS*CROPS;
        sample_kernel<<<(unsigned)((total+255)/256),256>>>(camera_imgs);
    }

    // conv1: M=64, Kpad=160, gather from padded crops
    hgemm<1,64,true,1><<<dim3((unsigned)(N1/128),1),256,SMEM_C1>>>(
        pw1, pcropsp, ph1, 0, 0, 0, 160, 0, (int)N1);
    // conv2: M=256, K=576 -> scatter to padded h2p
    hgemm<2,128,true,3><<<dim3((unsigned)(N2/128),2),256,SMEM_C2>>>(
        pw2, ph1, ph2p, 0, 0, 0, 576, 0, 0);
    // conv3: M=1024, K=2304 -> float h3 [oc][n] (R8 layout)
    hgemm<3,128,true,0><<<dim3((unsigned)(N3/128),8),256,SMEM_C3>>>(
        pw3, ph2p, ph3, 0, 0, 0, 2304, 0, (int)N3);

    tok_kernel<<<NIMG,256>>>(pos_embed);

    // S = tok0 @ M
    hgemm<0,128,false,0><<<dim3(8,3),256,SMEM_D>>>(
        ptok0, pMp, pS, 0, 0, 0, 1024, 1024, DIMK);

    attn_kernel<<<NIMG,256>>>();

    // EMB = CTX @ Wvo
    hgemm<0,128,false,0><<<dim3(8,3),256,SMEM_D>>>(
        pCTX, pWvop, pEMB, 0, 0, 0, 1024, 1024, DIMK);

    fuse_kernel<<<NBOX,256>>>(bdd, momentum, out);
}

// round 16
// speedup vs baseline: 1.1858x; 1.0071x over previous
#include <cuda_runtime.h>
#include <cuda_fp16.h>
#include <math.h>

#define DIMK   1024
#define IMG_H  512
#define IMG_W  1408
#define CROPS  224
#define NCC    6
#define NBB    32
#define NBOX   64
#define NIMG   384
#define O1 56
#define O2 14
#define O3 7
#define N1 ((long long)NIMG*O1*O1)   // 1204224
#define N2 ((long long)NIMG*O2*O2)   // 75264
#define N3 ((long long)NIMG*O3*O3)   // 18816
#define K1 147
#define K2 576
#define K3 2304
// padded crops: [ch][img][227][228]
#define CP_PW 228
#define CP_IMG (227*228)
#define CP_CH  (NIMG*CP_IMG)
// padded h2: [ic][img][15][15]
#define H2P_IMG 225
#define H2P_IC  (NIMG*H2P_IMG)

// ---------------- scratch ----------------
__device__ float  g_theta[NIMG*6];
__device__ int    g_valid[NIMG];
__device__ __align__(16) __half g_cropsp[3LL*CP_CH];
__device__ __half g_h1h[64LL*N1];
__device__ __align__(16) __half g_h2p[256LL*H2P_IC];
__device__ float  g_h3[1024LL*N3];               // [oc][n]
__device__ float  g_tok[(long long)NIMG*50*DIMK];
__device__ float  g_S[NIMG*DIMK];
__device__ float  g_EMB[NIMG*DIMK];
// packed paired layout: uint2 slots pair (kp, kp+4); slot s in 0..7:
//   kp_lo(s) = (s>=4 ? 8 : 0) + (s&3),  kp_hi = kp_lo + 4
__device__ unsigned g_wqp[512*1024], g_wvp[512*1024];
__device__ unsigned g_wkTp[512*1024], g_wop[512*1024];
__device__ unsigned g_Mp[512*1024], g_Wvop[512*1024];
__device__ unsigned g_w1p[64*80];
__device__ unsigned g_w2p[256*288];
__device__ unsigned g_w3p[1024*1152];
__device__ unsigned g_tok0p[384*512];
__device__ unsigned g_CTXp[384*512];

// ---------------- halo zero kernels ----------------
__global__ void haloc_kernel()
{
    long long base = (long long)blockIdx.x*CP_IMG;
    __half z = __ushort_as_half((unsigned short)0);
    for (int t = threadIdx.x; t < 3*CP_PW; t += 256) {
        int r = t/CP_PW, c = t - (t/CP_PW)*CP_PW;
        int row = (r == 0) ? 0 : (224 + r);
        g_cropsp[base + row*CP_PW + c] = z;
    }
    for (int t = threadIdx.x; t < 224*4; t += 256) {
        int row = 1 + (t >> 2); int c4 = t & 3;
        int col = (c4 == 0) ? 0 : (224 + c4);
        g_cropsp[base + row*CP_PW + col] = z;
    }
}
__global__ void haloh2_kernel()
{
    long long i = (long long)blockIdx.x*256 + threadIdx.x;
    if (i >= 256LL*NIMG*29) return;
    int e = (int)(i % 29); long long pair = i / 29;
    int off = (e < 15) ? (14*15 + e) : ((e - 15)*15 + 14);
    g_h2p[pair*225 + off] = __ushort_as_half((unsigned short)0);
}

// ---------------- pack kernels (paired uint2 layouts) ----------------
// A-form u32 linear index i: half=i&1; j=i>>1; mloc=j%BMp; j/=BMp; s=j%8;
//   j/=8; chunk=j%NCH; mblk=j/NCH; kp = kp_lo(s)+half*4; k = chunk*32+kp*2
__global__ void packA_kernel(const float* __restrict__ src, unsigned* __restrict__ dst,
                             int Ms, int Ks, int BMp, int Kpad, long long total)
{
    long long i = (long long)blockIdx.x*256 + threadIdx.x;
    if (i >= total) return;
    int NCH = Kpad/32;
    int half = (int)(i & 1); long long j = i >> 1;
    int mloc = (int)(j % BMp); j /= BMp;
    int s = (int)(j % 8); j /= 8;
    int chunk = (int)(j % NCH); int mblk = (int)(j / NCH);
    int kp = ((s >= 4) ? 8 : 0) + (s & 3) + half*4;
    int m = mblk*BMp + mloc, k = chunk*32 + kp*2;
    float v0 = (m < Ms && k   < Ks) ? src[(long long)m*Ks + k]   : 0.f;
    float v1 = (m < Ms && k+1 < Ks) ? src[(long long)m*Ks + k+1] : 0.f;
    __half2 h = __floats2half2_rn(v0, v1);
    dst[i] = *reinterpret_cast<unsigned*>(&h);
}

// merged qkvo pack. A-form for wq/wv; B-form for wkT/wo:
// B-form u32 idx: half=i&1; j=i>>1; n=j%1024; j/=1024; s=j%8; chunk=j/8
__global__ void packQKVO_kernel(const float* __restrict__ wq, const float* __restrict__ wv,
                                const float* __restrict__ wk, const float* __restrict__ wo,
                                unsigned* __restrict__ dq, unsigned* __restrict__ dv,
                                unsigned* __restrict__ dkT, unsigned* __restrict__ dwo)
{
    int sect = blockIdx.x >> 11;
    long long i = (long long)(blockIdx.x & 2047)*256 + threadIdx.x;
    if (i >= 512LL*1024) return;
    float v0, v1;
    unsigned* dst;
    int half = (int)(i & 1); long long j = i >> 1;
    if (sect < 2) {
        int mloc = (int)(j % 128); j /= 128;
        int s = (int)(j % 8); j /= 8;
        int chunk = (int)(j % 32); int mblk = (int)(j / 32);
        int kp = ((s >= 4) ? 8 : 0) + (s & 3) + half*4;
        int m = mblk*128 + mloc, k = chunk*32 + kp*2;
        const float* sp = (sect == 0) ? wq : wv;
        v0 = sp[(long long)m*1024 + k]; v1 = sp[(long long)m*1024 + k + 1];
        dst = (sect == 0) ? dq : dv;
    } else {
        int n = (int)(j % 1024); j /= 1024;
        int s = (int)(j % 8); int chunk = (int)(j / 8);
        int kp = ((s >= 4) ? 8 : 0) + (s & 3) + half*4;
        int k = chunk*32 + kp*2;
        if (sect == 2) { v0 = wk[(long long)n*1024 + k];  v1 = wk[(long long)n*1024 + k + 1];  dst = dkT; }
        else           { v0 = wo[(long long)k*1024 + n];  v1 = wo[(long long)(k+1)*1024 + n];  dst = dwo; }
    }
    __half2 h = __floats2half2_rn(v0, v1);
    dst[i] = *reinterpret_cast<unsigned*>(&h);
}

// ---------------- theta ----------------
__global__ void theta_kernel(const float* __restrict__ boxes, const float* __restrict__ la,
                             const float* __restrict__ l2i, const float* __restrict__ aug,
                             const float* __restrict__ thw, const float* __restrict__ thb)
{
    int t = blockIdx.x*blockDim.x + threadIdx.x;
    if (t >= NIMG) return;
    int c = t % NCC; int n = t / NCC; int b = n / NBB; int nb = n % NBB;
    const float* bx = boxes + (b*NBB + nb)*9;
    float r[4];
    #pragma unroll
    for (int i = 0; i < 4; i++) {
        float s = thb[i];
        #pragma unroll
        for (int j = 0; j < 9; j++) s += bx[j]*thw[i*9+j];
        r[i] = tanhf(s);
    }
    const float* L = la + b*16;
    float cx = bx[0]-L[3], cy = bx[1]-L[7], cz = bx[2]-L[11];
    float a00=L[0],a01=L[1],a02=L[2],a10=L[4],a11=L[5],a12=L[6],a20=L[8],a21=L[9],a22=L[10];
    float det = a00*(a11*a22-a12*a21) - a01*(a10*a22-a12*a20) + a02*(a10*a21-a11*a20);
    float id = 1.f/det;
    float x = ((a11*a22-a12*a21)*cx + (a02*a21-a01*a22)*cy + (a01*a12-a02*a11)*cz)*id;
    float y = ((a12*a20-a10*a22)*cx + (a00*a22-a02*a20)*cy + (a02*a10-a00*a12)*cz)*id;
    float z = ((a10*a21-a11*a20)*cx + (a01*a20-a00*a21)*cy + (a00*a11-a01*a10)*cz)*id;
    const float* P = l2i + (b*NCC + c)*16;
    float px = P[0]*x + P[1]*y + P[2]*z  + P[3];
    float py = P[4]*x + P[5]*y + P[6]*z  + P[7];
    float pz = P[8]*x + P[9]*y + P[10]*z + P[11];
    float zz = fminf(fmaxf(pz, 1e-5f), 100000.f);
    float qx = px/zz, qy = py/zz;
    const float* A = aug + (b*NCC + c)*16;
    float ux = A[0]*qx + A[1]*qy + A[2]*zz + A[3];
    float uy = A[4]*qx + A[5]*qy + A[6]*zz + A[7];
    int on = (uy < (float)IMG_H) && (uy >= 0.f) && (ux < (float)IMG_W) && (ux >= 0.f);
    g_theta[t*6+0]=r[0]; g_theta[t*6+1]=r[1]; g_theta[t*6+2]=ux/(float)IMG_W*2.f-1.f;
    g_theta[t*6+3]=r[2]; g_theta[t*6+4]=r[3]; g_theta[t*6+5]=uy/(float)IMG_H*2.f-1.f;
    g_valid[t] = on;
}

// ---------------- grid sample -> padded half crops ----------------
__global__ void sample_kernel(const float* __restrict__ imgs)
{
    long long idx = (long long)blockIdx.x*blockDim.x + threadIdx.x;
    if (idx >= (long long)NIMG*CROPS*CROPS) return;
    int x = (int)(idx % CROPS);
    int y = (int)((idx / CROPS) % CROPS);
    int ii = (int)(idx / (CROPS*CROPS));
    int c = ii % NCC; int n = ii / NCC; int b = n / NBB;
    float t0 = g_theta[ii*6+0], t1 = g_theta[ii*6+1], t2 = g_theta[ii*6+2];
    float t3 = g_theta[ii*6+3], t4 = g_theta[ii*6+4], t5 = g_theta[ii*6+5];
    float gx = (2.f*x + 1.f)/(float)CROPS - 1.f;
    float gy = (2.f*y + 1.f)/(float)CROPS - 1.f;
    float g0 = gx*t0 + gy*t1 + t2;
    float g1 = gx*t3 + gy*t4 + t5;
    float ixf = ((g0 + 1.f)*(float)IMG_W - 1.f)*0.5f;
    float iyf = ((g1 + 1.f)*(float)IMG_H - 1.f)*0.5f;
    float x0 = floorf(ixf), y0 = floorf(iyf);
    float wx = ixf - x0, wy = iyf - y0;
    float x1 = x0 + 1.f, y1 = y0 + 1.f;
    bool vx0 = (x0 >= 0.f) && (x0 <= (float)(IMG_W-1));
    bool vx1 = (x1 >= 0.f) && (x1 <= (float)(IMG_W-1));
    bool vy0 = (y0 >= 0.f) && (y0 <= (float)(IMG_H-1));
    bool vy1 = (y1 >= 0.f) && (y1 <= (float)(IMG_H-1));
    int xi0 = (int)fminf(fmaxf(x0,0.f),(float)(IMG_W-1));
    int xi1 = (int)fminf(fmaxf(x1,0.f),(float)(IMG_W-1));
    int yi0 = (int)fminf(fmaxf(y0,0.f),(float)(IMG_H-1));
    int yi1 = (int)fminf(fmaxf(y1,0.f),(float)(IMG_H-1));
    float w00=(1.f-wx)*(1.f-wy), w01=wx*(1.f-wy), w10=(1.f-wx)*wy, w11=wx*wy;
    const float* base = imgs + (long long)(b*NCC + c)*3LL*IMG_H*IMG_W;
    #pragma unroll
    for (int ch = 0; ch < 3; ch++) {
        const float* im = base + (long long)ch*IMG_H*IMG_W;
        float v00 = (vx0&&vy0) ? im[yi0*IMG_W + xi0] : 0.f;
        float v01 = (vx1&&vy0) ? im[yi0*IMG_W + xi1] : 0.f;
        float v10 = (vx0&&vy1) ? im[yi1*IMG_W + xi0] : 0.f;
        float v11 = (vx1&&vy1) ? im[yi1*IMG_W + xi1] : 0.f;
        g_cropsp[(long long)ch*CP_CH + (long long)ii*CP_IMG + (y+1)*CP_PW + (x+1)] =
            __float2half_rn(v00*w00 + v01*w01 + v10*w10 + v11*w11);
    }
}

// ---------------- cp.async helpers ----------------
__device__ __forceinline__ void cpasync16(unsigned dst, const void* src) {
    asm volatile("cp.async.cg.shared.global [%0], [%1], 16;\n"
        :: "r"(dst), "l"(src) : "memory");
}
#define CP_COMMIT() asm volatile("cp.async.commit_group;\n" ::: "memory")
#define CP_WAIT1()  asm volatile("cp.async.wait_group 1;\n" ::: "memory")

// =====================================================================
// Half-native pipelined GEMM, m16n8k16 fp16 MMA, fp32 accum.
// Paired uint2 smem tiles: slot s holds {kp_lo, kp_lo+4}; one LDS.64
// per fragment k-pair. A stride 132/68 uint2, B stride 132 uint2.
// CW: 0=float C, 1=half C, 2=packed-dense-B C, 3=scatter to h2p
// =====================================================================
template<int LOADER, int BM, bool RELU, int CW>
__global__ __launch_bounds__(256) void hgemm(
    const unsigned* __restrict__ A, const void* __restrict__ Bp, void* __restrict__ Cp,
    const unsigned* __restrict__ Ax, const void* __restrict__ Bpx, void* __restrict__ Cpx,
    int Kpad, int N, int ldc)
{
    if (blockIdx.z == 1) { A = Ax; Bp = Bpx; Cp = Cpx; }

    constexpr int SROW2 = BM + 4;          // A uint2 stride
    constexpr int BROW2 = 132;             // B uint2 stride
    constexpr int ASZ2  = 8*SROW2;         // uint2 per A stage
    constexpr int BSZ2  = 8*BROW2;
    extern __shared__ uint2 smem2[];
    int2* sTab = (int2*)(smem2 + 3*(ASZ2+BSZ2));

    const int tid = threadIdx.x;
    const int bx = blockIdx.x, by = blockIdx.y;
    const int lane = tid & 31, warp = tid >> 5;
    const int g = lane >> 2, tg = lane & 3;
    constexpr int WMC = BM/32;
    constexpr int WN  = 128/(8/WMC);
    constexpr int NT  = WN/8;
    const int wm = (warp % WMC)*32;
    const int wn = (warp / WMC)*WN;

    const int NCH = Kpad/32;
    const int T = NCH;

    const int nloc = tid & 127;
    const int ngl  = bx*128 + nloc;
    const int hsel = tid >> 7;
    const __half* Bh = (const __half*)Bp;
    const uint2* Bu2 = (const uint2*)Bp;
    const uint2* A2  = (const uint2*)A;

    const __half* Bbase = Bh;
    if (LOADER == 1) {
        int img = ngl/3136, pos = ngl - img*3136;
        int oy = pos/56, ox = pos - oy*56;
        Bbase = Bh + ((long long)img*CP_IMG + oy*4*CP_PW + ox*4);
    } else if (LOADER == 2) {
        int img = ngl/196, pos = ngl - img*196;
        int oy = pos/14, ox = pos - oy*14;
        Bbase = Bh + ((long long)img*3136 + oy*4*56 + ox*4);
    } else if (LOADER == 3) {
        int img = ngl/49, pos = ngl - img*49;
        int oy = pos/7, ox = pos - oy*7;
        Bbase = Bh + ((long long)img*H2P_IMG + oy*2*15 + ox*2);
    }

    if (LOADER != 0) {
        int TPK = Kpad/2;
        for (int kp = tid; kp < TPK; kp += 256) {
            int2 e;
            #pragma unroll
            for (int h = 0; h < 2; h++) {
                int k = kp*2 + h;
                int D = 0;
                if (LOADER == 1) {
                    if (k < K1) {
                        int ch = k/49, rr = k - ch*49;
                        int ky = rr/7, kx = rr - ky*7;
                        D = ch*CP_CH + ky*CP_PW + kx;
                    }
                } else if (LOADER == 2) {
                    int ic = k/9, rr = k - ic*9;
                    int ky = rr/3, kx = rr - ky*3;
                    D = ic*(int)N1 + ky*56 + kx;
                } else if (LOADER == 3) {
                    int ic = k/9, rr = k - ic*9;
                    int ky = rr/3, kx = rr - ky*3;
                    D = ic*H2P_IC + ky*15 + kx;
                }
                if (h == 0) e.x = D; else e.y = D;
            }
            sTab[kp] = e;
        }
        __syncthreads();
    }

    unsigned sbase = (unsigned)__cvta_generic_to_shared(smem2);

    unsigned Breg[8];
    auto gatherB = [&](int chunk) {
        #pragma unroll
        for (int j = 0; j < 8; j++) {
            int2 dd = sTab[chunk*16 + hsel*8 + j];
            unsigned v0 = (unsigned)__half_as_ushort(Bbase[dd.x]);
            unsigned v1 = (unsigned)__half_as_ushort(Bbase[dd.y]);
            Breg[j] = v0 | (v1 << 16);
        }
    };
    auto storeB = [&](int st) {
        uint2* sB = smem2 + st*(ASZ2+BSZ2) + ASZ2;
        #pragma unroll
        for (int j = 0; j < 4; j++) {
            // slot = hsel*4 + j pairs kp=hsel*8+j (lo) with kp+4 (hi)
            sB[(hsel*4 + j)*BROW2 + nloc] = make_uint2(Breg[j], Breg[j+4]);
        }
    };
    auto loadA_cp = [&](int st, int chunk) {
        unsigned sa = sbase + (unsigned)(st*(ASZ2+BSZ2)*8);
        constexpr int NTR = 4*BM;            // 16B transfers (2 uint2 each)
        #pragma unroll
        for (int i = 0; i < NTR/256; i++) {
            int e = tid + i*256;
            int slot = e / (BM/2), mq2 = (e % (BM/2))*2;
            const uint2* src = A2 + ((long long)(by*NCH + chunk)*8 + slot)*BM + mq2;
            cpasync16(sa + (unsigned)((slot*SROW2 + mq2)*8), src);
        }
    };
    auto loadB_cp = [&](int st, int chunk) {
        unsigned sb = sbase + (unsigned)((st*(ASZ2+BSZ2) + ASZ2)*8);
        #pragma unroll
        for (int i = 0; i < 2; i++) {
            int e = tid + i*256;
            int slot = e >> 6, nq2 = (e & 63)*2;
            const uint2* src = Bu2 + ((long long)(chunk*8 + slot))*N + bx*128 + nq2;
            cpasync16(sb + (unsigned)((slot*BROW2 + nq2)*8), src);
        }
    };

    float acc[2][NT][4];
    #pragma unroll
    for (int i=0;i<2;i++)
        #pragma unroll
        for (int j=0;j<NT;j++)
            #pragma unroll
            for (int q=0;q<4;q++) acc[i][j][q] = 0.f;

    if (LOADER == 0) {
        loadA_cp(0,0); loadB_cp(0,0); CP_COMMIT();
        loadA_cp(1,1); loadB_cp(1,1); CP_COMMIT();
    } else {
        gatherB(0); storeB(0);
        gatherB(1);
        loadA_cp(0,0); CP_COMMIT();
        loadA_cp(1,1); CP_COMMIT();
    }

    for (int kt = 0; kt < T; kt++) {
        CP_WAIT1();
        __syncthreads();
        int kn = kt + 2;
        if (kn < T) {
            int stn = kn % 3;
            loadA_cp(stn, kn);
            if (LOADER == 0) loadB_cp(stn, kn);
        }
        CP_COMMIT();

        int st = kt % 3;
        const uint2* sA = smem2 + st*(ASZ2+BSZ2);
        const uint2* sB = sA + ASZ2;
        #pragma unroll
        for (int s = 0; s < 2; s++) {
            int slotb = s*4 + tg;           // pairs (kb+tg, kb+tg+4)
            unsigned af[2][4];
            #pragma unroll
            for (int mt = 0; mt < 2; mt++) {
                int r1 = wm + mt*16 + g;
                uint2 aA = sA[slotb*SROW2 + r1];
                uint2 aB = sA[slotb*SROW2 + r1 + 8];
                af[mt][0] = aA.x; af[mt][2] = aA.y;
                af[mt][1] = aB.x; af[mt][3] = aB.y;
            }
            unsigned bf[NT][2];
            #pragma unroll
            for (int nt = 0; nt < NT; nt++) {
                int cc = wn + nt*8 + g;
                uint2 bb = sB[slotb*BROW2 + cc];
                bf[nt][0] = bb.x; bf[nt][1] = bb.y;
            }
            #pragma unroll
            for (int mt = 0; mt < 2; mt++)
                #pragma unroll
                for (int nt = 0; nt < NT; nt++) {
                    asm volatile(
                        "mma.sync.aligned.m16n8k16.row.col.f32.f16.f16.f32 "
                        "{%0,%1,%2,%3}, {%4,%5,%6,%7}, {%8,%9}, {%0,%1,%2,%3};\n"
                        : "+f"(acc[mt][nt][0]), "+f"(acc[mt][nt][1]),
                          "+f"(acc[mt][nt][2]), "+f"(acc[mt][nt][3])
                        : "r"(af[mt][0]), "r"(af[mt][1]), "r"(af[mt][2]), "r"(af[mt][3]),
                          "r"(bf[nt][0]), "r"(bf[nt][1]));
                }
        }
        if (LOADER != 0) {
            if (kt+1 < T) storeB((kt+1) % 3);
            if (kt+2 < T) gatherB(kt+2);
        }
    }

    #pragma unroll
    for (int mt = 0; mt < 2; mt++) {
        int r0 = by*BM + wm + mt*16 + g;
        #pragma unroll
        for (int nt = 0; nt < NT; nt++) {
            int c0 = bx*128 + wn + nt*8 + tg*2;
            float v0 = acc[mt][nt][0], v1 = acc[mt][nt][1];
            float v2 = acc[mt][nt][2], v3 = acc[mt][nt][3];
            if (RELU) { v0=fmaxf(v0,0.f); v1=fmaxf(v1,0.f); v2=fmaxf(v2,0.f); v3=fmaxf(v3,0.f); }
            if (CW == 0) {
                float* C = (float*)Cp;
                *reinterpret_cast<float2*>(C + (long long)r0*ldc + c0)     = make_float2(v0, v1);
                *reinterpret_cast<float2*>(C + (long long)(r0+8)*ldc + c0) = make_float2(v2, v3);
            } else if (CW == 1) {
                __half* C = (__half*)Cp;
                __half2 h0 = __floats2half2_rn(v0, v1);
                __half2 h1 = __floats2half2_rn(v2, v3);
                *reinterpret_cast<__half2*>(C + (long long)r0*ldc + c0)     = h0;
                *reinterpret_cast<__half2*>(C + (long long)(r0+8)*ldc + c0) = h1;
            } else if (CW == 2) {
                // packed-dense-B (paired): r = k of consumer
                __half* C = (__half*)Cp;
                auto st1 = [&](int r, int c, float v) {
                    int chunk = r >> 5, kpr = (r >> 1) & 15, e = r & 1;
                    int s2 = ((kpr >= 8) ? 4 : 0) + (kpr & 3);
                    int half = ((kpr & 7) >= 4) ? 1 : 0;
                    long long hidx = ((((long long)(chunk*8 + s2))*N + c)*2 + half)*2 + e;
                    C[hidx] = __float2half_rn(v);
                };
                st1(r0,   c0,   v0); st1(r0,   c0+1, v1);
                st1(r0+8, c0,   v2); st1(r0+8, c0+1, v3);
            } else {  // CW==3: scatter to padded h2p
                __half* C = (__half*)Cp;
                auto st2 = [&](int r, int c, float v) {
                    int img = c/196; int pos = c - img*196;
                    int oy = pos/14, ox = pos - oy*14;
                    C[(long long)r*H2P_IC + img*H2P_IMG + oy*15 + ox] = __float2half_rn(v);
                };
                st2(r0,   c0,   v0); st2(r0,   c0+1, v1);
                st2(r0+8, c0,   v2); st2(r0+8, c0+1, v3);
            }
        }
    }
}

// ---------------- tokens (packed cls in paired A-form) ----------
__global__ void tok_kernel(const float* __restrict__ pos_embed)
{
    int i = blockIdx.x;
    int mblk = i >> 7, mloc = i & 127;
    __half* tp = (__half*)g_tok0p;
    for (int d = threadIdx.x; d < DIMK; d += blockDim.x) {
        const float* hp = g_h3 + (long long)d*N3 + (long long)i*49;
        float s = 0.f;
        #pragma unroll 7
        for (int p = 0; p < 49; p++) {
            float v = hp[p];
            s += v;
            g_tok[((long long)i*50 + 1 + p)*DIMK + d] = v + pos_embed[(1+p)*DIMK + d];
        }
        float t0 = s*(1.f/49.f) + pos_embed[d];
        g_tok[(long long)i*50*DIMK + d] = t0;
        int chunk = d >> 5, kp = (d & 31) >> 1;
        int s2 = ((kp >= 8) ? 4 : 0) + (kp & 3);
        int half = ((kp & 7) >= 4) ? 1 : 0;
        long long hidx = ((((long long)(mblk*32 + chunk)*8 + s2)*128 + mloc)*2 + half)*2 + (d&1);
        tp[hidx] = __float2half_rn(t0);
    }
}

// ---------------- attention ----------------
__global__ void attn_kernel()
{
    int i = blockIdx.x;
    __shared__ float sS[DIMK];
    __shared__ float slog[64];
    const float* t = g_tok + (long long)i*50*DIMK;
    for (int d = threadIdx.x; d < DIMK; d += blockDim.x) sS[d] = g_S[i*DIMK + d];
    __syncthreads();
    int w = threadIdx.x >> 5, lane = threadIdx.x & 31;
    for (int j = w; j < 50; j += 8) {
        const float* tj = t + (long long)j*DIMK;
        float s = 0.f;
        for (int d = lane; d < DIMK; d += 32) s += sS[d]*tj[d];
        #pragma unroll
        for (int o = 16; o > 0; o >>= 1) s += __shfl_down_sync(0xffffffff, s, o);
        if (lane == 0) slog[j] = s * 0.03125f;
    }
    __syncthreads();
    if (threadIdx.x == 0) {
        float mx = slog[0];
        for (int j = 1; j < 50; j++) mx = fmaxf(mx, slog[j]);
        float sum = 0.f;
        for (int j = 0; j < 50; j++) { float e = expf(slog[j]-mx); slog[j]=e; sum+=e; }
        float inv = 1.f/sum;
        for (int j = 0; j < 50; j++) slog[j] *= inv;
    }
    __syncthreads();
    int mblk = i >> 7, mloc = i & 127;
    __half* cp = (__half*)g_CTXp;
    for (int d = threadIdx.x; d < DIMK; d += blockDim.x) {
        float c = 0.f;
        #pragma unroll 10
        for (int j = 0; j < 50; j++) c += slog[j]*t[(long long)j*DIMK + d];
        int chunk = d >> 5, kp = (d & 31) >> 1;
        int s2 = ((kp >= 8) ? 4 : 0) + (kp & 3);
        int half = ((kp & 7) >= 4) ? 1 : 0;
        long long hidx = ((((long long)(mblk*32 + chunk)*8 + s2)*128 + mloc)*2 + half)*2 + (d&1);
        cp[hidx] = __float2half_rn(c);
    }
}

// ---------------- final EMA fuse ----------------
__global__ void fuse_kernel(const float* __restrict__ bdd,
                            const float* __restrict__ momentum,
                            float* __restrict__ out)
{
    int n = blockIdx.x;
    float mom = *momentum;
    const int order[6] = {2,0,1,5,3,4};
    for (int d = threadIdx.x; d < DIMK; d += blockDim.x) {
        float e = bdd[d];
        #pragma unroll
        for (int k = 0; k < 6; k++) {
            int c = order[k];
            int ii = n*NCC + c;
            if (g_valid[ii]) e = mom*e + (1.f - mom)*g_EMB[(long long)ii*DIMK + d];
        }
        out[n*DIMK + d] = e;
    }
}

// ---------------- launch ----------------
static inline void* symv(const void* s) {
    void* p = nullptr; cudaGetSymbolAddress(&p, s); return p;
}
#define ABSZ128 ((8*(128+4) + 8*132)*8)
#define ABSZ64  ((8*(64+4)  + 8*132)*8)
#define SMEM_D   (3*ABSZ128)
#define SMEM_C1  (3*ABSZ64  + 80*8)
#define SMEM_C2  (3*ABSZ128 + 288*8)
#define SMEM_C3  (3*ABSZ128 + 1152*8)

extern "C" void kernel_launch(void* const* d_in, const int* in_sizes, int n_in,
                              void* d_out, int out_size)
{
    const float* camera_imgs = (const float*)d_in[0];
    const float* pred_boxes  = (const float*)d_in[1];
    const float* img_aug     = (const float*)d_in[2];
    const float* lidar_aug   = (const float*)d_in[3];
    const float* lidar2img   = (const float*)d_in[4];
    const float* momentum    = (const float*)d_in[5];
    const float* bdd         = (const float*)d_in[6];
    const float* theta_w     = (const float*)d_in[7];
    const float* theta_b     = (const float*)d_in[8];
    const float* conv1       = (const float*)d_in[9];
    const float* conv2       = (const float*)d_in[10];
    const float* conv3       = (const float*)d_in[11];
    const float* pos_embed   = (const float*)d_in[12];
    const float* wq          = (const float*)d_in[13];
    const float* wk          = (const float*)d_in[14];
    const float* wv          = (const float*)d_in[15];
    const float* wo          = (const float*)d_in[16];
    float* out = (float*)d_out;

    unsigned* pwqp = (unsigned*)symv(g_wqp);
    unsigned* pwvp = (unsigned*)symv(g_wvp);
    unsigned* pwkT = (unsigned*)symv(g_wkTp);
    unsigned* pwop = (unsigned*)symv(g_wop);
    unsigned* pMp  = (unsigned*)symv(g_Mp);
    unsigned* pWvop= (unsigned*)symv(g_Wvop);
    unsigned* pw1  = (unsigned*)symv(g_w1p);
    unsigned* pw2  = (unsigned*)symv(g_w2p);
    unsigned* pw3  = (unsigned*)symv(g_w3p);
    unsigned* ptok0= (unsigned*)symv(g_tok0p);
    unsigned* pCTX = (unsigned*)symv(g_CTXp);
    __half* pcropsp= (__half*)symv(g_cropsp);
    __half* ph1    = (__half*)symv(g_h1h);
    __half* ph2p   = (__half*)symv(g_h2p);
    float*  ph3    = (float*)symv(g_h3);
    float*  pS     = (float*)symv(g_S);
    float*  pEMB   = (float*)symv(g_EMB);

    cudaFuncSetAttribute(hgemm<0,128,false,2>, cudaFuncAttributeMaxDynamicSharedMemorySize, SMEM_D);
    cudaFuncSetAttribute(hgemm<0,128,false,0>, cudaFuncAttributeMaxDynamicSharedMemorySize, SMEM_D);
    cudaFuncSetAttribute(hgemm<1,64, true, 1>, cudaFuncAttributeMaxDynamicSharedMemorySize, SMEM_C1);
    cudaFuncSetAttribute(hgemm<2,128,true, 3>, cudaFuncAttributeMaxDynamicSharedMemorySize, SMEM_C2);
    cudaFuncSetAttribute(hgemm<3,128,true, 0>, cudaFuncAttributeMaxDynamicSharedMemorySize, SMEM_C3);

    // ---- halo zeros ----
    haloc_kernel<<<3*NIMG,256>>>();
    haloh2_kernel<<<(unsigned)((256LL*NIMG*29 + 255)/256),256>>>();

    // ---- pack weights ----
    packQKVO_kernel<<<4*2048,256>>>(wq, wv, wk, wo, pwqp, pwvp, pwkT, pwop);
    packA_kernel<<<20,256>>>(conv1, pw1, 64, K1, 64, 160, 64LL*80);
    packA_kernel<<<288,256>>>(conv2, pw2, 256, K2, 128, 576, 256LL*288);
    packA_kernel<<<4608,256>>>(conv3, pw3, 1024, K3, 128, 2304, 1024LL*1152);

    // ---- M = wq@wk^T ; Wvo = wv@wo : merged via gridDim.z = 2 ----
    hgemm<0,128,false,2><<<dim3(8,8,2),256,SMEM_D>>>(
        pwqp, pwkT, pMp, pwvp, pwop, pWvop, 1024, 1024, 1024);

    theta_kernel<<<2,192>>>(pred_boxes, lidar_aug, lidar2img, img_aug, theta_w, theta_b);
    {
        long long total = (long long)NIMG*CROPS*CROPS;
        sample_kernel<<<(unsigned)((total+255)/256),256>>>(camera_imgs);
    }

    // conv1: M=64, Kpad=160, gather from padded crops
    hgemm<1,64,true,1><<<dim3((unsigned)(N1/128),1),256,SMEM_C1>>>(
        pw1, pcropsp, ph1, 0, 0, 0, 160, 0, (int)N1);
    // conv2: M=256, K=576 -> scatter to padded h2p
    hgemm<2,128,true,3><<<dim3((unsigned)(N2/128),2),256,SMEM_C2>>>(
        pw2, ph1, ph2p, 0, 0, 0, 576, 0, 0);
    // conv3: M=1024, K=2304 -> float h3 [oc][n]
    hgemm<3,128,true,0><<<dim3((unsigned)(N3/128),8),256,SMEM_C3>>>(
        pw3, ph2p, ph3, 0, 0, 0, 2304, 0, (int)N3);

    tok_kernel<<<NIMG,256>>>(pos_embed);

    // S = tok0 @ M
    hgemm<0,128,false,0><<<dim3(8,3),256,SMEM_D>>>(
        ptok0, pMp, pS, 0, 0, 0, 1024, 1024, DIMK);

    attn_kernel<<<NIMG,256>>>();

    // EMB = CTX @ Wvo
    hgemm<0,128,false,0><<<dim3(8,3),256,SMEM_D>>>(
        pCTX, pWvop, pEMB, 0, 0, 0, 1024, 1024, DIMK);

    fuse_kernel<<<NBOX,256>>>(bdd, momentum, out);
}